// round 1
// baseline (speedup 1.0000x reference)
#include <cuda_runtime.h>

#define NMAX 50000
#define EMAXE 400000
#define ETOTMAX (EMAXE + NMAX)

// Scratch (static device globals — allocation-free)
__device__ float    g_A[NMAX * 256];      // feature buffer (layer input / aggregation output)
__device__ float    g_B[NMAX * 256];      // transformed features h = A @ W
__device__ float    g_ssrc[NMAX * 4];     // per-node src attention logits [N,H]
__device__ float    g_sdst[NMAX * 4];     // per-node dst attention logits [N,H]
__device__ unsigned g_emax[NMAX * 4];     // segment max (monotone-uint mapped)
__device__ float    g_denom[NMAX * 4];    // segment softmax denominator
__device__ float    g_escr[ETOTMAX * 4];  // per-edge logits / exp scratch [Etot,H]

// ---- monotone float<->uint order-preserving map (for atomicMax on floats) ----
__device__ __forceinline__ unsigned fmap(float f) {
    unsigned u = __float_as_uint(f);
    return (u & 0x80000000u) ? ~u : (u | 0x80000000u);
}
__device__ __forceinline__ float funmap(unsigned u) {
    return (u & 0x80000000u) ? __uint_as_float(u & 0x7FFFFFFFu) : __uint_as_float(~u);
}
#define EMAX_INIT 0x007FFFFFu  // fmap(-inf)

// ---- init: zero aggregation target + reset segment max/denom ----
__global__ void init_layer(float* o, int o_elems, int nH) {
    int stride = gridDim.x * blockDim.x;
    for (int j = blockIdx.x * blockDim.x + threadIdx.x; j < o_elems; j += stride) o[j] = 0.f;
    for (int j = blockIdx.x * blockDim.x + threadIdx.x; j < nH; j += stride) {
        g_emax[j] = EMAX_INIT;
        g_denom[j] = 0.f;
    }
}

// ---- layer 1 GEMM: x[N,3] @ W[3,256] -> out[N,256] ----
__global__ void gemm_l1(const float* __restrict__ x, const float* __restrict__ W,
                        float* __restrict__ out, int n) {
    __shared__ float xs[3];
    int node = blockIdx.x;
    if (node >= n) return;
    if (threadIdx.x < 3) xs[threadIdx.x] = x[node * 3 + threadIdx.x];
    __syncthreads();
    int c = threadIdx.x;  // 256 threads = 256 cols
    float acc = xs[0] * W[c] + xs[1] * W[256 + c] + xs[2] * W[512 + c];
    out[(size_t)node * 256 + c] = acc;
}

// ---- generic fp32 SGEMM: A[M,K] @ Bw[K,N] -> C[M,N]; BM=64,BN=64,BK=16, 256 thr ----
__global__ void sgemm(const float* __restrict__ A, const float* __restrict__ Bw,
                      float* __restrict__ C, int M, int N, int K) {
    __shared__ float As[16][64];
    __shared__ float Bs[16][64];
    int tid = threadIdx.x;
    int bm = blockIdx.x * 64, bn = blockIdx.y * 64;
    int tx = tid & 15, ty = tid >> 4;
    float acc[4][4] = {};
    for (int k0 = 0; k0 < K; k0 += 16) {
        // A tile: 64x16, one float4 per thread
        {
            int m = tid >> 2, k4 = (tid & 3) * 4;
            float4 v = make_float4(0.f, 0.f, 0.f, 0.f);
            if (bm + m < M) v = *(const float4*)&A[(size_t)(bm + m) * K + k0 + k4];
            As[k4 + 0][m] = v.x; As[k4 + 1][m] = v.y; As[k4 + 2][m] = v.z; As[k4 + 3][m] = v.w;
        }
        // B tile: 16x64, one float4 per thread
        {
            int k = tid >> 4, c4 = (tid & 15) * 4;
            float4 v = make_float4(0.f, 0.f, 0.f, 0.f);
            if (bn + c4 < N) v = *(const float4*)&Bw[(size_t)(k0 + k) * N + bn + c4];
            *(float4*)&Bs[k][c4] = v;
        }
        __syncthreads();
#pragma unroll
        for (int k = 0; k < 16; k++) {
            float a[4], b[4];
#pragma unroll
            for (int i = 0; i < 4; i++) a[i] = As[k][ty * 4 + i];
#pragma unroll
            for (int j = 0; j < 4; j++) b[j] = Bs[k][tx * 4 + j];
#pragma unroll
            for (int i = 0; i < 4; i++)
#pragma unroll
                for (int j = 0; j < 4; j++) acc[i][j] += a[i] * b[j];
        }
        __syncthreads();
    }
#pragma unroll
    for (int i = 0; i < 4; i++) {
        int m = bm + ty * 4 + i;
        if (m < M) {
#pragma unroll
            for (int j = 0; j < 4; j++) {
                int c = bn + tx * 4 + j;
                if (c < N) C[(size_t)m * N + c] = acc[i][j];
            }
        }
    }
}

// ---- per-node attention logits: s[n,h] = sum_c h[n,h,c] * a[h,c] (warp per (n,h)) ----
__global__ void attn_s(const float* __restrict__ h, const float* __restrict__ a_src,
                       const float* __restrict__ a_dst, int n, int H, int C) {
    int w = (blockIdx.x * blockDim.x + threadIdx.x) >> 5;
    int lane = threadIdx.x & 31;
    if (w >= n * H) return;
    int node = w / H, hd = w % H;
    const float* hp = h + (size_t)node * H * C + hd * C;
    float s1 = 0.f, s2 = 0.f;
    for (int c = lane; c < C; c += 32) {
        float v = hp[c];
        s1 += v * a_src[hd * C + c];
        s2 += v * a_dst[hd * C + c];
    }
#pragma unroll
    for (int o = 16; o; o >>= 1) {
        s1 += __shfl_xor_sync(0xFFFFFFFFu, s1, o);
        s2 += __shfl_xor_sync(0xFFFFFFFFu, s2, o);
    }
    if (!lane) { g_ssrc[w] = s1; g_sdst[w] = s2; }
}

// ---- edge pass 1: leaky_relu logits -> scratch, segment max via mapped atomicMax ----
__global__ void edge_logits(const int* __restrict__ ei, int E, int Etot, int H) {
    int e = blockIdx.x * blockDim.x + threadIdx.x;
    if (e >= Etot) return;
    int s, d;
    if (e < E) { s = ei[e]; d = ei[E + e]; } else { s = d = e - E; }
    for (int h = 0; h < H; h++) {
        float v = g_ssrc[s * H + h] + g_sdst[d * H + h];
        v = v >= 0.f ? v : 0.2f * v;
        g_escr[e * H + h] = v;
        atomicMax(&g_emax[d * H + h], fmap(v));
    }
}

// ---- edge pass 2: exp(e - max) -> scratch, segment sum denominator ----
__global__ void edge_exp(const int* __restrict__ ei, int E, int Etot, int H) {
    int e = blockIdx.x * blockDim.x + threadIdx.x;
    if (e >= Etot) return;
    int d = (e < E) ? ei[E + e] : e - E;
    for (int h = 0; h < H; h++) {
        float m = funmap(g_emax[d * H + h]);
        float ex = __expf(g_escr[e * H + h] - m);
        g_escr[e * H + h] = ex;
        atomicAdd(&g_denom[d * H + h], ex);
    }
}

// ---- edge pass 3: out[dst] += alpha * h[src]  (warp per edge, vec4 red) ----
__global__ void edge_aggr(const int* __restrict__ ei, const float* __restrict__ h,
                          float* __restrict__ out, int E, int Etot, int H, int C) {
    int w = (blockIdx.x * blockDim.x + threadIdx.x) >> 5;
    int lane = threadIdx.x & 31;
    if (w >= Etot) return;
    int s, d;
    if (w < E) { s = ei[w]; d = ei[E + w]; } else { s = d = w - E; }
    int HC4 = (H * C) >> 2;
    const float4* hp = (const float4*)(h + (size_t)s * H * C);
    float4* op = (float4*)(out + (size_t)d * H * C);
    for (int ch = lane; ch < HC4; ch += 32) {
        int hd = (ch * 4) / C;
        float alpha = g_escr[w * H + hd] / g_denom[d * H + hd];
        float4 v = hp[ch];
        v.x *= alpha; v.y *= alpha; v.z *= alpha; v.w *= alpha;
        asm volatile("red.global.add.v4.f32 [%0], {%1,%2,%3,%4};"
                     :: "l"(op + ch), "f"(v.x), "f"(v.y), "f"(v.z), "f"(v.w) : "memory");
    }
}

// ---- bias (+ optional relu) ----
__global__ void bias_act(float* __restrict__ o, const float* __restrict__ b,
                         int n, int HC, int do_relu) {
    int total = n * HC;
    int stride = gridDim.x * blockDim.x;
    for (int i = blockIdx.x * blockDim.x + threadIdx.x; i < total; i += stride) {
        float v = o[i] + b[i % HC];
        o[i] = do_relu ? fmaxf(v, 0.f) : v;
    }
}

extern "C" void kernel_launch(void* const* d_in, const int* in_sizes, int n_in,
                              void* d_out, int out_size) {
    const float* x      = (const float*)d_in[0];
    const int*   ei     = (const int*)d_in[1];
    const float* W1     = (const float*)d_in[2];
    const float* a_src1 = (const float*)d_in[3];
    const float* a_dst1 = (const float*)d_in[4];
    const float* b1     = (const float*)d_in[5];
    const float* W2     = (const float*)d_in[6];
    const float* a_src2 = (const float*)d_in[7];
    const float* a_dst2 = (const float*)d_in[8];
    const float* b2     = (const float*)d_in[9];
    const float* W3     = (const float*)d_in[10];
    const float* a_src3 = (const float*)d_in[11];
    const float* a_dst3 = (const float*)d_in[12];
    const float* b3     = (const float*)d_in[13];
    float* out = (float*)d_out;

    int n = in_sizes[0] / 3;
    int E = in_sizes[1] / 2;
    int Etot = E + n;

    float *gA, *gB;
    cudaGetSymbolAddress((void**)&gA, g_A);
    cudaGetSymbolAddress((void**)&gB, g_B);

    int eb = (Etot + 255) / 256;                 // edge kernels, thread per edge
    int ewb = (Etot + 7) / 8;                    // edge kernels, warp per edge
    int swb4 = (n * 4 + 7) / 8;                  // attn_s warps, H=4
    int swb1 = (n * 1 + 7) / 8;                  // attn_s warps, H=1
    dim3 g2((n + 63) / 64, (256 + 63) / 64);     // sgemm layer 2
    dim3 g3((n + 63) / 64, (32 + 63) / 64);      // sgemm layer 3

    // ================= Layer 1: x[N,3] -> [N,256], H=4, C=64, relu =================
    init_layer<<<4096, 256>>>(gA, n * 256, n * 4);
    gemm_l1<<<n, 256>>>(x, W1, gB, n);
    attn_s<<<swb4, 256>>>(gB, a_src1, a_dst1, n, 4, 64);
    edge_logits<<<eb, 256>>>(ei, E, Etot, 4);
    edge_exp<<<eb, 256>>>(ei, E, Etot, 4);
    edge_aggr<<<ewb, 256>>>(ei, gB, gA, E, Etot, 4, 64);
    bias_act<<<4096, 256>>>(gA, b1, n, 256, 1);

    // ================= Layer 2: [N,256] -> [N,256], H=4, C=64, relu ================
    sgemm<<<g2, 256>>>(gA, W2, gB, n, 256, 256);
    init_layer<<<4096, 256>>>(gA, n * 256, n * 4);
    attn_s<<<swb4, 256>>>(gB, a_src2, a_dst2, n, 4, 64);
    edge_logits<<<eb, 256>>>(ei, E, Etot, 4);
    edge_exp<<<eb, 256>>>(ei, E, Etot, 4);
    edge_aggr<<<ewb, 256>>>(ei, gB, gA, E, Etot, 4, 64);
    bias_act<<<4096, 256>>>(gA, b2, n, 256, 1);

    // ================= Layer 3: [N,256] -> [N,32], H=1, C=32, no relu ==============
    sgemm<<<g3, 256>>>(gA, W3, gB, n, 32, 256);
    init_layer<<<4096, 256>>>(out, n * 32, n * 1);
    attn_s<<<swb1, 256>>>(gB, a_src3, a_dst3, n, 1, 32);
    edge_logits<<<eb, 256>>>(ei, E, Etot, 1);
    edge_exp<<<eb, 256>>>(ei, E, Etot, 1);
    edge_aggr<<<ewb, 256>>>(ei, gB, out, E, Etot, 1, 32);
    bias_act<<<4096, 256>>>(out, b3, n, 32, 0);
}

// round 4
// speedup vs baseline: 1.5032x; 1.5032x over previous
#include <cuda_runtime.h>

#define NMAX 50000
#define EMAXE 400000
#define ETOTMAX (EMAXE + NMAX)

// Scratch (static device globals — allocation-free)
__device__ float    g_A[NMAX * 256];      // feature buffer (layer input / aggregation output)
__device__ float    g_B[NMAX * 256];      // transformed features h = A @ W
__device__ float    g_ssrc[NMAX * 4];     // per-node src attention logits [N,H]
__device__ float    g_sdst[NMAX * 4];     // per-node dst attention logits [N,H]
__device__ unsigned g_emax[NMAX * 4];     // segment max (monotone-uint mapped)
__device__ float    g_denom[NMAX * 4];    // segment softmax denominator
__device__ float    g_escr[ETOTMAX * 4];  // per-edge logits / exp scratch [Etot,H]

// ---- monotone float<->uint order-preserving map (for atomicMax on floats) ----
__device__ __forceinline__ unsigned fmap(float f) {
    unsigned u = __float_as_uint(f);
    return (u & 0x80000000u) ? ~u : (u | 0x80000000u);
}
__device__ __forceinline__ float funmap(unsigned u) {
    return (u & 0x80000000u) ? __uint_as_float(u & 0x7FFFFFFFu) : __uint_as_float(~u);
}
#define EMAX_INIT 0x007FFFFFu  // fmap(-inf)

__device__ __forceinline__ unsigned f2tf32(float f) {
    unsigned u;
    asm("cvt.rna.tf32.f32 %0, %1;" : "=r"(u) : "f"(f));
    return u;
}

// ---- init: zero aggregation target + reset segment max/denom ----
__global__ void init_layer(float* o, int o_elems, int nH) {
    int stride = gridDim.x * blockDim.x;
    for (int j = blockIdx.x * blockDim.x + threadIdx.x; j < o_elems; j += stride) o[j] = 0.f;
    for (int j = blockIdx.x * blockDim.x + threadIdx.x; j < nH; j += stride) {
        g_emax[j] = EMAX_INIT;
        g_denom[j] = 0.f;
    }
}

// ---- layer 1 GEMM: x[N,3] @ W[3,256] -> out[N,256] ----
__global__ void gemm_l1(const float* __restrict__ x, const float* __restrict__ W,
                        float* __restrict__ out, int n) {
    __shared__ float xs[3];
    int node = blockIdx.x;
    if (node >= n) return;
    if (threadIdx.x < 3) xs[threadIdx.x] = x[node * 3 + threadIdx.x];
    __syncthreads();
    int c = threadIdx.x;
    float acc = xs[0] * W[c] + xs[1] * W[256 + c] + xs[2] * W[512 + c];
    out[(size_t)node * 256 + c] = acc;
}

// =====================================================================
// tf32 tensor-core GEMM: A[M,K] @ Bw[K,N] -> C[M,N]
// block tile 128x128, 8 warps (4 m x 2 n), warp tile 32x64
// mma.sync.aligned.m16n8k8.row.col.f32.tf32.tf32.f32
// =====================================================================
#define APAD 20   // As row stride (floats): conflict-free for frag loads
#define BPAD 136  // Bs row stride (floats): conflict-free for frag loads

__global__ __launch_bounds__(256) void mma_gemm(
    const float* __restrict__ A, const float* __restrict__ Bw,
    float* __restrict__ C, int M, int N, int K) {
    __shared__ float As[128 * APAD];  // [m][k], 128 x 16 (padded)
    __shared__ float Bs[16 * BPAD];   // [k][n], 16 x 128 (padded)

    int tid = threadIdx.x;
    int warp = tid >> 5, lane = tid & 31;
    int gid = lane >> 2, tig = lane & 3;
    int wm = warp & 3, wn = warp >> 2;  // 4 x 2 warp grid
    int bm = blockIdx.x * 128, bn = blockIdx.y * 128;

    float acc[2][8][4];
#pragma unroll
    for (int i = 0; i < 2; i++)
#pragma unroll
        for (int j = 0; j < 8; j++)
#pragma unroll
            for (int r = 0; r < 4; r++) acc[i][j][r] = 0.f;

    for (int k0 = 0; k0 < K; k0 += 16) {
        // Load A tile: 128x16 = 512 float4, 2 per thread
#pragma unroll
        for (int r = 0; r < 2; r++) {
            int s = tid * 2 + r;
            int m = s >> 2, k4 = (s & 3) * 4;
            float4 v = make_float4(0.f, 0.f, 0.f, 0.f);
            if (bm + m < M) v = *(const float4*)&A[(size_t)(bm + m) * K + k0 + k4];
            float* p = &As[m * APAD + k4];
            p[0] = __uint_as_float(f2tf32(v.x));
            p[1] = __uint_as_float(f2tf32(v.y));
            p[2] = __uint_as_float(f2tf32(v.z));
            p[3] = __uint_as_float(f2tf32(v.w));
        }
        // Load B tile: 16x128 = 512 float4, 2 per thread
#pragma unroll
        for (int r = 0; r < 2; r++) {
            int s = tid * 2 + r;
            int k = s >> 5, c4 = (s & 31) * 4;
            float4 v = make_float4(0.f, 0.f, 0.f, 0.f);
            if (bn + c4 < N) v = *(const float4*)&Bw[(size_t)(k0 + k) * N + bn + c4];
            float* p = &Bs[k * BPAD + c4];
            p[0] = __uint_as_float(f2tf32(v.x));
            p[1] = __uint_as_float(f2tf32(v.y));
            p[2] = __uint_as_float(f2tf32(v.z));
            p[3] = __uint_as_float(f2tf32(v.w));
        }
        __syncthreads();

#pragma unroll
        for (int kk = 0; kk < 16; kk += 8) {
            unsigned af[2][4], bf[8][2];
#pragma unroll
            for (int mt = 0; mt < 2; mt++) {
                int row = wm * 32 + mt * 16 + gid;
                af[mt][0] = __float_as_uint(As[row * APAD + kk + tig]);
                af[mt][1] = __float_as_uint(As[(row + 8) * APAD + kk + tig]);
                af[mt][2] = __float_as_uint(As[row * APAD + kk + tig + 4]);
                af[mt][3] = __float_as_uint(As[(row + 8) * APAD + kk + tig + 4]);
            }
#pragma unroll
            for (int nt = 0; nt < 8; nt++) {
                int col = wn * 64 + nt * 8 + gid;
                bf[nt][0] = __float_as_uint(Bs[(kk + tig) * BPAD + col]);
                bf[nt][1] = __float_as_uint(Bs[(kk + tig + 4) * BPAD + col]);
            }
#pragma unroll
            for (int mt = 0; mt < 2; mt++)
#pragma unroll
                for (int nt = 0; nt < 8; nt++) {
                    asm volatile(
                        "mma.sync.aligned.m16n8k8.row.col.f32.tf32.tf32.f32 "
                        "{%0,%1,%2,%3}, {%4,%5,%6,%7}, {%8,%9}, {%0,%1,%2,%3};"
                        : "+f"(acc[mt][nt][0]), "+f"(acc[mt][nt][1]),
                          "+f"(acc[mt][nt][2]), "+f"(acc[mt][nt][3])
                        : "r"(af[mt][0]), "r"(af[mt][1]), "r"(af[mt][2]), "r"(af[mt][3]),
                          "r"(bf[nt][0]), "r"(bf[nt][1]));
                }
        }
        __syncthreads();
    }

    // Store C
#pragma unroll
    for (int mt = 0; mt < 2; mt++) {
#pragma unroll
        for (int nt = 0; nt < 8; nt++) {
            int col = bn + wn * 64 + nt * 8 + 2 * tig;
            if (col >= N) continue;
            int row0 = bm + wm * 32 + mt * 16 + gid;
            if (row0 < M)
                *(float2*)&C[(size_t)row0 * N + col] =
                    make_float2(acc[mt][nt][0], acc[mt][nt][1]);
            if (row0 + 8 < M)
                *(float2*)&C[(size_t)(row0 + 8) * N + col] =
                    make_float2(acc[mt][nt][2], acc[mt][nt][3]);
        }
    }
}

// ---- per-node attention logits: s[n,h] = sum_c h[n,h,c] * a[h,c] (warp per (n,h)) ----
__global__ void attn_s(const float* __restrict__ h, const float* __restrict__ a_src,
                       const float* __restrict__ a_dst, int n, int H, int C) {
    int w = (blockIdx.x * blockDim.x + threadIdx.x) >> 5;
    int lane = threadIdx.x & 31;
    if (w >= n * H) return;
    int node = w / H, hd = w % H;
    const float* hp = h + (size_t)node * H * C + hd * C;
    float s1 = 0.f, s2 = 0.f;
    for (int c = lane; c < C; c += 32) {
        float v = hp[c];
        s1 += v * a_src[hd * C + c];
        s2 += v * a_dst[hd * C + c];
    }
#pragma unroll
    for (int o = 16; o; o >>= 1) {
        s1 += __shfl_xor_sync(0xFFFFFFFFu, s1, o);
        s2 += __shfl_xor_sync(0xFFFFFFFFu, s2, o);
    }
    if (!lane) { g_ssrc[w] = s1; g_sdst[w] = s2; }
}

// ========================= edge passes, H=4 vectorized =========================
__global__ void edge_logits4(const int* __restrict__ ei, int E, int Etot) {
    int e = blockIdx.x * blockDim.x + threadIdx.x;
    if (e >= Etot) return;
    int s, d;
    if (e < E) { s = ei[e]; d = ei[E + e]; } else { s = d = e - E; }
    float4 vs = *(const float4*)&g_ssrc[s * 4];
    float4 vd = *(const float4*)&g_sdst[d * 4];
    float4 v;
    v.x = vs.x + vd.x; v.x = v.x >= 0.f ? v.x : 0.2f * v.x;
    v.y = vs.y + vd.y; v.y = v.y >= 0.f ? v.y : 0.2f * v.y;
    v.z = vs.z + vd.z; v.z = v.z >= 0.f ? v.z : 0.2f * v.z;
    v.w = vs.w + vd.w; v.w = v.w >= 0.f ? v.w : 0.2f * v.w;
    *(float4*)&g_escr[e * 4] = v;
    atomicMax(&g_emax[d * 4 + 0], fmap(v.x));
    atomicMax(&g_emax[d * 4 + 1], fmap(v.y));
    atomicMax(&g_emax[d * 4 + 2], fmap(v.z));
    atomicMax(&g_emax[d * 4 + 3], fmap(v.w));
}

__global__ void edge_exp4(const int* __restrict__ ei, int E, int Etot) {
    int e = blockIdx.x * blockDim.x + threadIdx.x;
    if (e >= Etot) return;
    int d = (e < E) ? ei[E + e] : e - E;
    float4 v = *(const float4*)&g_escr[e * 4];
    float4 ex;
    ex.x = __expf(v.x - funmap(g_emax[d * 4 + 0]));
    ex.y = __expf(v.y - funmap(g_emax[d * 4 + 1]));
    ex.z = __expf(v.z - funmap(g_emax[d * 4 + 2]));
    ex.w = __expf(v.w - funmap(g_emax[d * 4 + 3]));
    *(float4*)&g_escr[e * 4] = ex;
    asm volatile("red.global.add.v4.f32 [%0], {%1,%2,%3,%4};"
                 :: "l"(&g_denom[d * 4]), "f"(ex.x), "f"(ex.y), "f"(ex.z), "f"(ex.w)
                 : "memory");
}

// ---- aggregation H=4,C=64: warp per edge, alpha via shuffle ----
__global__ void edge_aggr4(const int* __restrict__ ei, const float* __restrict__ h,
                           float* __restrict__ out, int E, int Etot) {
    int w = (blockIdx.x * blockDim.x + threadIdx.x) >> 5;
    int lane = threadIdx.x & 31;
    if (w >= Etot) return;
    int s, d;
    if (w < E) { s = ei[w]; d = ei[E + w]; } else { s = d = w - E; }
    float a_h = 0.f;
    if (lane < 4) a_h = g_escr[w * 4 + lane] / g_denom[d * 4 + lane];
    const float4* hp = (const float4*)(h + (size_t)s * 256);
    float4* op = (float4*)(out + (size_t)d * 256);
#pragma unroll
    for (int it = 0; it < 2; it++) {
        int ch = lane + it * 32;                      // float4 index 0..63
        float alpha = __shfl_sync(0xFFFFFFFFu, a_h, ch >> 4);
        float4 v = hp[ch];
        v.x *= alpha; v.y *= alpha; v.z *= alpha; v.w *= alpha;
        asm volatile("red.global.add.v4.f32 [%0], {%1,%2,%3,%4};"
                     :: "l"(op + ch), "f"(v.x), "f"(v.y), "f"(v.z), "f"(v.w) : "memory");
    }
}

// ========================= edge passes, H=1 (layer 3) =========================
__global__ void edge_logits1(const int* __restrict__ ei, int E, int Etot) {
    int e = blockIdx.x * blockDim.x + threadIdx.x;
    if (e >= Etot) return;
    int s, d;
    if (e < E) { s = ei[e]; d = ei[E + e]; } else { s = d = e - E; }
    float v = g_ssrc[s] + g_sdst[d];
    v = v >= 0.f ? v : 0.2f * v;
    g_escr[e] = v;
    atomicMax(&g_emax[d], fmap(v));
}

__global__ void edge_exp1(const int* __restrict__ ei, int E, int Etot) {
    int e = blockIdx.x * blockDim.x + threadIdx.x;
    if (e >= Etot) return;
    int d = (e < E) ? ei[E + e] : e - E;
    float ex = __expf(g_escr[e] - funmap(g_emax[d]));
    g_escr[e] = ex;
    atomicAdd(&g_denom[d], ex);
}

// ---- aggregation H=1,C=32: 8 lanes per edge ----
__global__ void edge_aggr1(const int* __restrict__ ei, const float* __restrict__ h,
                           float* __restrict__ out, int E, int Etot) {
    int idx = blockIdx.x * blockDim.x + threadIdx.x;
    int w = idx >> 3;           // edge
    int lane = idx & 7;         // float4 slot 0..7 (32 floats)
    if (w >= Etot) return;
    int s, d;
    if (w < E) { s = ei[w]; d = ei[E + w]; } else { s = d = w - E; }
    float alpha = g_escr[w] / g_denom[d];
    const float4* hp = (const float4*)(h + (size_t)s * 32);
    float4* op = (float4*)(out + (size_t)d * 32);
    float4 v = hp[lane];
    v.x *= alpha; v.y *= alpha; v.z *= alpha; v.w *= alpha;
    asm volatile("red.global.add.v4.f32 [%0], {%1,%2,%3,%4};"
                 :: "l"(op + lane), "f"(v.x), "f"(v.y), "f"(v.z), "f"(v.w) : "memory");
}

// ---- bias (+ optional relu) ----
__global__ void bias_act(float* __restrict__ o, const float* __restrict__ b,
                         int n, int HC, int do_relu) {
    int total = n * HC;
    int stride = gridDim.x * blockDim.x;
    for (int i = blockIdx.x * blockDim.x + threadIdx.x; i < total; i += stride) {
        float v = o[i] + b[i % HC];
        o[i] = do_relu ? fmaxf(v, 0.f) : v;
    }
}

extern "C" void kernel_launch(void* const* d_in, const int* in_sizes, int n_in,
                              void* d_out, int out_size) {
    const float* x      = (const float*)d_in[0];
    const int*   ei     = (const int*)d_in[1];
    const float* W1     = (const float*)d_in[2];
    const float* a_src1 = (const float*)d_in[3];
    const float* a_dst1 = (const float*)d_in[4];
    const float* b1     = (const float*)d_in[5];
    const float* W2     = (const float*)d_in[6];
    const float* a_src2 = (const float*)d_in[7];
    const float* a_dst2 = (const float*)d_in[8];
    const float* b2     = (const float*)d_in[9];
    const float* W3     = (const float*)d_in[10];
    const float* a_src3 = (const float*)d_in[11];
    const float* a_dst3 = (const float*)d_in[12];
    const float* b3     = (const float*)d_in[13];
    float* out = (float*)d_out;

    int n = in_sizes[0] / 3;
    int E = in_sizes[1] / 2;
    int Etot = E + n;

    float *gA, *gB;
    cudaGetSymbolAddress((void**)&gA, g_A);
    cudaGetSymbolAddress((void**)&gB, g_B);

    int eb = (Etot + 255) / 256;                 // thread per edge
    int ewb = (Etot + 7) / 8;                    // warp per edge
    int e8b = (Etot * 8 + 255) / 256;            // 8 threads per edge
    int swb4 = (n * 4 + 7) / 8;
    int swb1 = (n * 1 + 7) / 8;
    dim3 g2((n + 127) / 128, 2);                 // mma gemm: N=256
    dim3 g3((n + 127) / 128, 1);                 // mma gemm: N=32

    // ================= Layer 1: x[N,3] -> [N,256], H=4, C=64, relu =================
    init_layer<<<4096, 256>>>(gA, n * 256, n * 4);
    gemm_l1<<<n, 256>>>(x, W1, gB, n);
    attn_s<<<swb4, 256>>>(gB, a_src1, a_dst1, n, 4, 64);
    edge_logits4<<<eb, 256>>>(ei, E, Etot);
    edge_exp4<<<eb, 256>>>(ei, E, Etot);
    edge_aggr4<<<ewb, 256>>>(ei, gB, gA, E, Etot);
    bias_act<<<4096, 256>>>(gA, b1, n, 256, 1);

    // ================= Layer 2: [N,256] -> [N,256], H=4, C=64, relu ================
    mma_gemm<<<g2, 256>>>(gA, W2, gB, n, 256, 256);
    init_layer<<<4096, 256>>>(gA, n * 256, n * 4);
    attn_s<<<swb4, 256>>>(gB, a_src2, a_dst2, n, 4, 64);
    edge_logits4<<<eb, 256>>>(ei, E, Etot);
    edge_exp4<<<eb, 256>>>(ei, E, Etot);
    edge_aggr4<<<ewb, 256>>>(ei, gB, gA, E, Etot);
    bias_act<<<4096, 256>>>(gA, b2, n, 256, 1);

    // ================= Layer 3: [N,256] -> [N,32], H=1, C=32, no relu ==============
    mma_gemm<<<g3, 256>>>(gA, W3, gB, n, 32, 256);
    init_layer<<<4096, 256>>>(out, n * 32, n * 1);
    attn_s<<<swb1, 256>>>(gB, a_src3, a_dst3, n, 1, 32);
    edge_logits1<<<eb, 256>>>(ei, E, Etot);
    edge_exp1<<<eb, 256>>>(ei, E, Etot);
    edge_aggr1<<<e8b, 256>>>(ei, gB, out, E, Etot);
    bias_act<<<4096, 256>>>(out, b3, n, 32, 0);
}

// round 5
// speedup vs baseline: 1.5597x; 1.0376x over previous
#include <cuda_runtime.h>

#define NMAX 50000
#define EMAXE 400000
#define ETOTMAX (EMAXE + NMAX)
#define NEG_INF __int_as_float(0xff800000)

// Scratch (static device globals — allocation-free)
__device__ float g_A[NMAX * 256];       // feature buffer
__device__ float g_B[NMAX * 256];       // transformed features h = A @ W
__device__ float g_ssrc[NMAX * 4];      // per-node src attention logits [N,H]
__device__ float g_sdst[NMAX * 4];      // per-node dst attention logits [N,H]
__device__ int   g_csr_src[ETOTMAX];    // CSR: src ids grouped by dst
__device__ int   g_rowptr[NMAX + 1];    // CSR row pointers
__device__ int   g_wptr[NMAX];          // counts / write cursors
__device__ int   g_blksum[260];         // scan partials

__device__ __forceinline__ unsigned f2tf32(float f) {
    unsigned u;
    asm("cvt.rna.tf32.f32 %0, %1;" : "=r"(u) : "f"(f));
    return u;
}

// ============================ CSR construction ============================
__global__ void csr_init(int n) {
    int i = blockIdx.x * blockDim.x + threadIdx.x;
    if (i < n) g_wptr[i] = 1;  // self-loop contributes 1 to every in-degree
}

__global__ void csr_count(const int* __restrict__ ei, int E) {
    int e = blockIdx.x * blockDim.x + threadIdx.x;
    if (e < E) atomicAdd(&g_wptr[ei[E + e]], 1);
}

__global__ void scan_part(int n) {
    __shared__ int sm[256];
    int i = blockIdx.x * 256 + threadIdx.x;
    sm[threadIdx.x] = (i < n) ? g_wptr[i] : 0;
    __syncthreads();
    for (int o = 128; o; o >>= 1) {
        if (threadIdx.x < o) sm[threadIdx.x] += sm[threadIdx.x + o];
        __syncthreads();
    }
    if (!threadIdx.x) g_blksum[blockIdx.x] = sm[0];
}

__global__ void scan_top(int nb) {
    __shared__ int sm[260];
    if (threadIdx.x < nb) sm[threadIdx.x] = g_blksum[threadIdx.x];
    __syncthreads();
    if (!threadIdx.x) {
        int run = 0;
        for (int j = 0; j < nb; j++) { int t = sm[j]; sm[j] = run; run += t; }
    }
    __syncthreads();
    if (threadIdx.x < nb) g_blksum[threadIdx.x] = sm[threadIdx.x];
}

__global__ void scan_fin(int n) {
    __shared__ int sm[256];
    int base = blockIdx.x * 256;
    int i = base + threadIdx.x;
    sm[threadIdx.x] = (i < n) ? g_wptr[i] : 0;
    __syncthreads();
    if (!threadIdx.x) {
        int run = g_blksum[blockIdx.x];
        for (int j = 0; j < 256; j++) { int t = sm[j]; sm[j] = run; run += t; }
        if (base + 256 >= n) g_rowptr[n] = run;  // only last block
    }
    __syncthreads();
    if (i < n) { g_rowptr[i] = sm[threadIdx.x]; g_wptr[i] = 0; }
}

__global__ void csr_fill(const int* __restrict__ ei, int E, int Etot) {
    int e = blockIdx.x * blockDim.x + threadIdx.x;
    if (e >= Etot) return;
    int s, d;
    if (e < E) { s = ei[e]; d = ei[E + e]; } else { s = d = e - E; }
    int pos = atomicAdd(&g_wptr[d], 1);
    g_csr_src[g_rowptr[d] + pos] = s;
}

// ============== layer 1 GEMM + fused attention logits ==============
// x[N,3] @ W[3,256] -> out[N,256]; also s_src/s_dst per (node,head)
__global__ void gemm_l1_attn(const float* __restrict__ x, const float* __restrict__ W,
                             const float* __restrict__ asrc, const float* __restrict__ adst,
                             float* __restrict__ out, int n) {
    __shared__ float xs[3];
    __shared__ float r1[8], r2[8];
    int node = blockIdx.x;
    if (node >= n) return;
    int tid = threadIdx.x;
    if (tid < 3) xs[tid] = x[node * 3 + tid];
    __syncthreads();
    float acc = xs[0] * W[tid] + xs[1] * W[256 + tid] + xs[2] * W[512 + tid];
    out[(size_t)node * 256 + tid] = acc;
    // attention partials: a_src is [4][64] contiguous = [tid]
    float p1 = acc * asrc[tid];
    float p2 = acc * adst[tid];
#pragma unroll
    for (int o = 16; o; o >>= 1) {
        p1 += __shfl_xor_sync(0xFFFFFFFFu, p1, o);
        p2 += __shfl_xor_sync(0xFFFFFFFFu, p2, o);
    }
    int warp = tid >> 5, lane = tid & 31;
    if (!lane) { r1[warp] = p1; r2[warp] = p2; }
    __syncthreads();
    if (tid < 4) {
        g_ssrc[node * 4 + tid] = r1[tid * 2] + r1[tid * 2 + 1];
        g_sdst[node * 4 + tid] = r2[tid * 2] + r2[tid * 2 + 1];
    }
}

// =====================================================================
// tf32 tensor-core GEMM (unchanged from R4 — proven): 128x128 tile
// =====================================================================
#define APAD 20
#define BPAD 136

__global__ __launch_bounds__(256) void mma_gemm(
    const float* __restrict__ A, const float* __restrict__ Bw,
    float* __restrict__ C, int M, int N, int K) {
    __shared__ float As[128 * APAD];
    __shared__ float Bs[16 * BPAD];

    int tid = threadIdx.x;
    int warp = tid >> 5, lane = tid & 31;
    int gid = lane >> 2, tig = lane & 3;
    int wm = warp & 3, wn = warp >> 2;
    int bm = blockIdx.x * 128, bn = blockIdx.y * 128;

    float acc[2][8][4];
#pragma unroll
    for (int i = 0; i < 2; i++)
#pragma unroll
        for (int j = 0; j < 8; j++)
#pragma unroll
            for (int r = 0; r < 4; r++) acc[i][j][r] = 0.f;

    for (int k0 = 0; k0 < K; k0 += 16) {
#pragma unroll
        for (int r = 0; r < 2; r++) {
            int s = tid * 2 + r;
            int m = s >> 2, k4 = (s & 3) * 4;
            float4 v = make_float4(0.f, 0.f, 0.f, 0.f);
            if (bm + m < M) v = *(const float4*)&A[(size_t)(bm + m) * K + k0 + k4];
            float* p = &As[m * APAD + k4];
            p[0] = __uint_as_float(f2tf32(v.x));
            p[1] = __uint_as_float(f2tf32(v.y));
            p[2] = __uint_as_float(f2tf32(v.z));
            p[3] = __uint_as_float(f2tf32(v.w));
        }
#pragma unroll
        for (int r = 0; r < 2; r++) {
            int s = tid * 2 + r;
            int k = s >> 5, c4 = (s & 31) * 4;
            float4 v = make_float4(0.f, 0.f, 0.f, 0.f);
            if (bn + c4 < N) v = *(const float4*)&Bw[(size_t)(k0 + k) * N + bn + c4];
            float* p = &Bs[k * BPAD + c4];
            p[0] = __uint_as_float(f2tf32(v.x));
            p[1] = __uint_as_float(f2tf32(v.y));
            p[2] = __uint_as_float(f2tf32(v.z));
            p[3] = __uint_as_float(f2tf32(v.w));
        }
        __syncthreads();

#pragma unroll
        for (int kk = 0; kk < 16; kk += 8) {
            unsigned af[2][4], bf[8][2];
#pragma unroll
            for (int mt = 0; mt < 2; mt++) {
                int row = wm * 32 + mt * 16 + gid;
                af[mt][0] = __float_as_uint(As[row * APAD + kk + tig]);
                af[mt][1] = __float_as_uint(As[(row + 8) * APAD + kk + tig]);
                af[mt][2] = __float_as_uint(As[row * APAD + kk + tig + 4]);
                af[mt][3] = __float_as_uint(As[(row + 8) * APAD + kk + tig + 4]);
            }
#pragma unroll
            for (int nt = 0; nt < 8; nt++) {
                int col = wn * 64 + nt * 8 + gid;
                bf[nt][0] = __float_as_uint(Bs[(kk + tig) * BPAD + col]);
                bf[nt][1] = __float_as_uint(Bs[(kk + tig + 4) * BPAD + col]);
            }
#pragma unroll
            for (int mt = 0; mt < 2; mt++)
#pragma unroll
                for (int nt = 0; nt < 8; nt++) {
                    asm volatile(
                        "mma.sync.aligned.m16n8k8.row.col.f32.tf32.tf32.f32 "
                        "{%0,%1,%2,%3}, {%4,%5,%6,%7}, {%8,%9}, {%0,%1,%2,%3};"
                        : "+f"(acc[mt][nt][0]), "+f"(acc[mt][nt][1]),
                          "+f"(acc[mt][nt][2]), "+f"(acc[mt][nt][3])
                        : "r"(af[mt][0]), "r"(af[mt][1]), "r"(af[mt][2]), "r"(af[mt][3]),
                          "r"(bf[nt][0]), "r"(bf[nt][1]));
                }
        }
        __syncthreads();
    }

#pragma unroll
    for (int mt = 0; mt < 2; mt++) {
#pragma unroll
        for (int nt = 0; nt < 8; nt++) {
            int col = bn + wn * 64 + nt * 8 + 2 * tig;
            if (col >= N) continue;
            int row0 = bm + wm * 32 + mt * 16 + gid;
            if (row0 < M)
                *(float2*)&C[(size_t)row0 * N + col] =
                    make_float2(acc[mt][nt][0], acc[mt][nt][1]);
            if (row0 + 8 < M)
                *(float2*)&C[(size_t)(row0 + 8) * N + col] =
                    make_float2(acc[mt][nt][2], acc[mt][nt][3]);
        }
    }
}

// ---- per-node attention logits (layers 2,3): warp per (n,h) ----
__global__ void attn_s(const float* __restrict__ h, const float* __restrict__ a_src,
                       const float* __restrict__ a_dst, int n, int H, int C) {
    int w = (blockIdx.x * blockDim.x + threadIdx.x) >> 5;
    int lane = threadIdx.x & 31;
    if (w >= n * H) return;
    int node = w / H, hd = w % H;
    const float* hp = h + (size_t)node * H * C + hd * C;
    float s1 = 0.f, s2 = 0.f;
    for (int c = lane; c < C; c += 32) {
        float v = hp[c];
        s1 += v * a_src[hd * C + c];
        s2 += v * a_dst[hd * C + c];
    }
#pragma unroll
    for (int o = 16; o; o >>= 1) {
        s1 += __shfl_xor_sync(0xFFFFFFFFu, s1, o);
        s2 += __shfl_xor_sync(0xFFFFFFFFu, s2, o);
    }
    if (!lane) { g_ssrc[w] = s1; g_sdst[w] = s2; }
}

// =====================================================================
// Fused GAT propagate (H=4, C=64): block per dst node, 256 threads.
// Chunked online softmax + aggregation, no atomics, single store/elem.
// =====================================================================
#define CAP 256

__global__ __launch_bounds__(256) void gat_fused4(
    const float* __restrict__ h, const float* __restrict__ bias,
    float* __restrict__ out, int do_relu) {
    __shared__ float lw[CAP * 4];
    __shared__ int   ssrc[CAP];
    __shared__ float sh_m[4], sh_s[4], sh_f[4], sh_tmp[4];

    int node = blockIdx.x;
    int tid = threadIdx.x;
    int hd = tid >> 6;  // head for this channel

    int e0 = g_rowptr[node], e1 = g_rowptr[node + 1];
    float acc = 0.f;
    if (tid < 4) { sh_m[tid] = NEG_INF; sh_s[tid] = 0.f; }
    __syncthreads();

    for (int c0 = e0; c0 < e1; c0 += CAP) {
        int cs = min(CAP, e1 - c0);
        // load src ids
        for (int i = tid; i < cs; i += 256) ssrc[i] = g_csr_src[c0 + i];
        __syncthreads();
        // logits: leaky_relu(s_src[src][h] + s_dst[node][h])
        for (int i = tid; i < cs * 4; i += 256) {
            int e = i >> 2, hh = i & 3;
            float v = g_ssrc[ssrc[e] * 4 + hh] + g_sdst[node * 4 + hh];
            lw[i] = v >= 0.f ? v : 0.2f * v;
        }
        __syncthreads();
        // per-head chunk max (warp per head, threads 0..127)
        if (tid < 128) {
            int hh = tid >> 5, lane = tid & 31;
            float pm = NEG_INF;
            for (int e = lane; e < cs; e += 32) pm = fmaxf(pm, lw[e * 4 + hh]);
#pragma unroll
            for (int o = 16; o; o >>= 1) pm = fmaxf(pm, __shfl_xor_sync(0xFFFFFFFFu, pm, o));
            if (!lane) sh_tmp[hh] = pm;
        }
        __syncthreads();
        // merge with running max, compute rescale factor
        if (tid < 4) {
            float mold = sh_m[tid];
            float mnew = fmaxf(mold, sh_tmp[tid]);
            float f = __expf(mold - mnew);  // mold=-inf -> 0 (mnew finite: deg>=1)
            sh_f[tid] = f;
            sh_m[tid] = mnew;
            sh_s[tid] *= f;
        }
        __syncthreads();
        acc *= sh_f[hd];
        // exponentiate weights
        for (int i = tid; i < cs * 4; i += 256)
            lw[i] = __expf(lw[i] - sh_m[i & 3]);
        __syncthreads();
        // per-head chunk sum
        if (tid < 128) {
            int hh = tid >> 5, lane = tid & 31;
            float ps = 0.f;
            for (int e = lane; e < cs; e += 32) ps += lw[e * 4 + hh];
#pragma unroll
            for (int o = 16; o; o >>= 1) ps += __shfl_xor_sync(0xFFFFFFFFu, ps, o);
            if (!lane) sh_tmp[hh] = ps;
        }
        __syncthreads();
        if (tid < 4) sh_s[tid] += sh_tmp[tid];
        // aggregate: coalesced gather of h[src] rows, smem-broadcast weights
#pragma unroll 4
        for (int e = 0; e < cs; e++) {
            float w = lw[e * 4 + hd];
            acc += w * h[(size_t)ssrc[e] * 256 + tid];
        }
        __syncthreads();
    }
    float v = acc / sh_s[hd] + bias[tid];
    out[(size_t)node * 256 + tid] = do_relu ? fmaxf(v, 0.f) : v;
}

// =====================================================================
// Fused GAT propagate (H=1, C=32): warp per dst node, all-shuffle.
// =====================================================================
__global__ void gat_fused1(const float* __restrict__ h, const float* __restrict__ bias,
                           float* __restrict__ out, int n) {
    int w = (blockIdx.x * blockDim.x + threadIdx.x) >> 5;
    int lane = threadIdx.x & 31;
    if (w >= n) return;
    int node = w;
    int e0 = g_rowptr[node], e1 = g_rowptr[node + 1];
    float sdst = g_sdst[node];
    float m = NEG_INF, s = 0.f, acc = 0.f;
    for (int c0 = e0; c0 < e1; c0 += 32) {
        int cs = min(32, e1 - c0);
        int src = (lane < cs) ? g_csr_src[c0 + lane] : 0;
        float v = NEG_INF;
        if (lane < cs) {
            v = g_ssrc[src] + sdst;
            v = v >= 0.f ? v : 0.2f * v;
        }
        float cm = v;
#pragma unroll
        for (int o = 16; o; o >>= 1) cm = fmaxf(cm, __shfl_xor_sync(0xFFFFFFFFu, cm, o));
        float mnew = fmaxf(m, cm);
        float f = __expf(m - mnew);  // first chunk: m=-inf -> 0
        acc *= f; s *= f; m = mnew;
        float wv = (lane < cs) ? __expf(v - m) : 0.f;
        float ps = wv;
#pragma unroll
        for (int o = 16; o; o >>= 1) ps += __shfl_xor_sync(0xFFFFFFFFu, ps, o);
        s += ps;
        for (int e = 0; e < cs; e++) {
            float we = __shfl_sync(0xFFFFFFFFu, wv, e);
            int se = __shfl_sync(0xFFFFFFFFu, src, e);
            acc += we * h[(size_t)se * 32 + lane];
        }
    }
    out[(size_t)node * 32 + lane] = acc / s + bias[lane];
}

extern "C" void kernel_launch(void* const* d_in, const int* in_sizes, int n_in,
                              void* d_out, int out_size) {
    const float* x      = (const float*)d_in[0];
    const int*   ei     = (const int*)d_in[1];
    const float* W1     = (const float*)d_in[2];
    const float* a_src1 = (const float*)d_in[3];
    const float* a_dst1 = (const float*)d_in[4];
    const float* b1     = (const float*)d_in[5];
    const float* W2     = (const float*)d_in[6];
    const float* a_src2 = (const float*)d_in[7];
    const float* a_dst2 = (const float*)d_in[8];
    const float* b2     = (const float*)d_in[9];
    const float* W3     = (const float*)d_in[10];
    const float* a_src3 = (const float*)d_in[11];
    const float* a_dst3 = (const float*)d_in[12];
    const float* b3     = (const float*)d_in[13];
    float* out = (float*)d_out;

    int n = in_sizes[0] / 3;
    int E = in_sizes[1] / 2;
    int Etot = E + n;

    float *gA, *gB;
    cudaGetSymbolAddress((void**)&gA, g_A);
    cudaGetSymbolAddress((void**)&gB, g_B);

    int nb = (n + 255) / 256;
    int swb4 = (n * 4 + 7) / 8;
    int swb1 = (n * 1 + 7) / 8;
    dim3 g2((n + 127) / 128, 2);
    dim3 g3((n + 127) / 128, 1);

    // ---------------- CSR build (shared by all layers) ----------------
    csr_init<<<nb, 256>>>(n);
    csr_count<<<(E + 255) / 256, 256>>>(ei, E);
    scan_part<<<nb, 256>>>(n);
    scan_top<<<1, 256>>>(nb);
    scan_fin<<<nb, 256>>>(n);
    csr_fill<<<(Etot + 255) / 256, 256>>>(ei, E, Etot);

    // ---------------- Layer 1: x[N,3] -> [N,256], relu ----------------
    gemm_l1_attn<<<n, 256>>>(x, W1, a_src1, a_dst1, gB, n);
    gat_fused4<<<n, 256>>>(gB, b1, gA, 1);

    // ---------------- Layer 2: [N,256] -> [N,256], relu ---------------
    mma_gemm<<<g2, 256>>>(gA, W2, gB, n, 256, 256);
    attn_s<<<swb4, 256>>>(gB, a_src2, a_dst2, n, 4, 64);
    gat_fused4<<<n, 256>>>(gB, b2, gA, 1);

    // ---------------- Layer 3: [N,256] -> [N,32], mean ----------------
    mma_gemm<<<g3, 256>>>(gA, W3, gB, n, 32, 256);
    attn_s<<<swb1, 256>>>(gB, a_src3, a_dst3, n, 1, 32);
    gat_fused1<<<(n * 32 + 255) / 256, 256>>>(gB, b3, out, n);
}

// round 6
// speedup vs baseline: 2.4177x; 1.5501x over previous
#include <cuda_runtime.h>

#define NMAX 50000
#define EMAXE 400000
#define ETOTMAX (EMAXE + NMAX)
#define NEG_INF __int_as_float(0xff800000)

// Scratch (static device globals — allocation-free)
__device__ float g_A[NMAX * 256];       // feature buffer
__device__ float g_B[NMAX * 256];       // transformed features h = A @ W
__device__ float g_ssrc[NMAX * 4];      // per-node src attention logits [N,H]
__device__ float g_sdst[NMAX * 4];      // per-node dst attention logits [N,H]
__device__ int   g_csr_src[ETOTMAX];    // CSR: src ids grouped by dst
__device__ int   g_rowptr[NMAX + 1];    // CSR row pointers
__device__ int   g_wptr[NMAX];          // counts / write cursors
__device__ int   g_blksum[260];         // scan partials

__device__ __forceinline__ unsigned f2tf32(float f) {
    unsigned u;
    asm("cvt.rna.tf32.f32 %0, %1;" : "=r"(u) : "f"(f));
    return u;
}

__device__ __forceinline__ float pick4(float4 v, int i) {
    float ab = (i & 1) ? v.y : v.x;
    float cd = (i & 1) ? v.w : v.z;
    return (i & 2) ? cd : ab;
}

// ============================ CSR construction ============================
__global__ void csr_init(int n) {
    int i = blockIdx.x * blockDim.x + threadIdx.x;
    if (i < n) g_wptr[i] = 1;  // self-loop contributes 1 to every in-degree
}

__global__ void csr_count(const int* __restrict__ ei, int E) {
    int e = blockIdx.x * blockDim.x + threadIdx.x;
    if (e < E) atomicAdd(&g_wptr[ei[E + e]], 1);
}

__global__ void scan_part(int n) {
    __shared__ int sm[256];
    int i = blockIdx.x * 256 + threadIdx.x;
    sm[threadIdx.x] = (i < n) ? g_wptr[i] : 0;
    __syncthreads();
    for (int o = 128; o; o >>= 1) {
        if (threadIdx.x < o) sm[threadIdx.x] += sm[threadIdx.x + o];
        __syncthreads();
    }
    if (!threadIdx.x) g_blksum[blockIdx.x] = sm[0];
}

// parallel exclusive scan over <=256 block sums
__global__ void scan_top(int nb) {
    __shared__ int sm[256];
    int tid = threadIdx.x;
    int v = (tid < nb) ? g_blksum[tid] : 0;
    sm[tid] = v;
    __syncthreads();
#pragma unroll
    for (int o = 1; o < 256; o <<= 1) {
        int t = (tid >= o) ? sm[tid - o] : 0;
        __syncthreads();
        sm[tid] += t;
        __syncthreads();
    }
    if (tid < nb) g_blksum[tid] = sm[tid] - v;  // exclusive
}

// parallel per-block scan + global offset
__global__ void scan_fin(int n) {
    __shared__ int sm[256];
    int base = blockIdx.x * 256, tid = threadIdx.x, i = base + tid;
    int v = (i < n) ? g_wptr[i] : 0;
    sm[tid] = v;
    __syncthreads();
#pragma unroll
    for (int o = 1; o < 256; o <<= 1) {
        int t = (tid >= o) ? sm[tid - o] : 0;
        __syncthreads();
        sm[tid] += t;
        __syncthreads();
    }
    int incl = sm[tid];
    int off = g_blksum[blockIdx.x];
    if (i < n) { g_rowptr[i] = off + incl - v; g_wptr[i] = 0; }
    if (i == n - 1) g_rowptr[n] = off + incl;
}

__global__ void csr_fill(const int* __restrict__ ei, int E, int Etot) {
    int e = blockIdx.x * blockDim.x + threadIdx.x;
    if (e >= Etot) return;
    int s, d;
    if (e < E) { s = ei[e]; d = ei[E + e]; } else { s = d = e - E; }
    int pos = atomicAdd(&g_wptr[d], 1);
    g_csr_src[g_rowptr[d] + pos] = s;
}

// ============== layer 1 GEMM + fused attention logits ==============
__global__ void gemm_l1_attn(const float* __restrict__ x, const float* __restrict__ W,
                             const float* __restrict__ asrc, const float* __restrict__ adst,
                             float* __restrict__ out, int n) {
    __shared__ float xs[3];
    __shared__ float r1[8], r2[8];
    int node = blockIdx.x;
    if (node >= n) return;
    int tid = threadIdx.x;
    if (tid < 3) xs[tid] = x[node * 3 + tid];
    __syncthreads();
    float acc = xs[0] * W[tid] + xs[1] * W[256 + tid] + xs[2] * W[512 + tid];
    out[(size_t)node * 256 + tid] = acc;
    float p1 = acc * asrc[tid];
    float p2 = acc * adst[tid];
#pragma unroll
    for (int o = 16; o; o >>= 1) {
        p1 += __shfl_xor_sync(0xFFFFFFFFu, p1, o);
        p2 += __shfl_xor_sync(0xFFFFFFFFu, p2, o);
    }
    int warp = tid >> 5, lane = tid & 31;
    if (!lane) { r1[warp] = p1; r2[warp] = p2; }
    __syncthreads();
    if (tid < 4) {
        g_ssrc[node * 4 + tid] = r1[tid * 2] + r1[tid * 2 + 1];
        g_sdst[node * 4 + tid] = r2[tid * 2] + r2[tid * 2 + 1];
    }
}

// =====================================================================
// tf32 tensor-core GEMM, double-buffered smem, 1 sync per K-iter
// =====================================================================
#define APAD 20
#define BPAD 136

__global__ __launch_bounds__(256) void mma_gemm(
    const float* __restrict__ A, const float* __restrict__ Bw,
    float* __restrict__ C, int M, int N, int K) {
    __shared__ float As[2][128 * APAD];
    __shared__ float Bs[2][16 * BPAD];

    int tid = threadIdx.x;
    int warp = tid >> 5, lane = tid & 31;
    int gid = lane >> 2, tig = lane & 3;
    int wm = warp & 3, wn = warp >> 2;
    int bm = blockIdx.x * 128, bn = blockIdx.y * 128;

    // per-thread load coords
    int am0 = (tid * 2) >> 2, ak0 = ((tid * 2) & 3) * 4;
    int am1 = (tid * 2 + 1) >> 2, ak1 = ((tid * 2 + 1) & 3) * 4;
    int bk0 = (tid * 2) >> 5, bc0 = ((tid * 2) & 31) * 4;
    int bk1 = (tid * 2 + 1) >> 5, bc1 = ((tid * 2 + 1) & 31) * 4;

    float acc[2][8][4];
#pragma unroll
    for (int i = 0; i < 2; i++)
#pragma unroll
        for (int j = 0; j < 8; j++)
#pragma unroll
            for (int r = 0; r < 4; r++) acc[i][j][r] = 0.f;

    float4 ra0, ra1, rb0, rb1;
    // prefetch k0 = 0
    {
        ra0 = make_float4(0.f, 0.f, 0.f, 0.f);
        ra1 = ra0; rb0 = ra0; rb1 = ra0;
        if (bm + am0 < M) ra0 = *(const float4*)&A[(size_t)(bm + am0) * K + ak0];
        if (bm + am1 < M) ra1 = *(const float4*)&A[(size_t)(bm + am1) * K + ak1];
        if (bn + bc0 < N) rb0 = *(const float4*)&Bw[(size_t)bk0 * N + bn + bc0];
        if (bn + bc1 < N) rb1 = *(const float4*)&Bw[(size_t)bk1 * N + bn + bc1];
    }
    // store buffer 0
    {
        float* p = &As[0][am0 * APAD + ak0];
        p[0] = __uint_as_float(f2tf32(ra0.x)); p[1] = __uint_as_float(f2tf32(ra0.y));
        p[2] = __uint_as_float(f2tf32(ra0.z)); p[3] = __uint_as_float(f2tf32(ra0.w));
        p = &As[0][am1 * APAD + ak1];
        p[0] = __uint_as_float(f2tf32(ra1.x)); p[1] = __uint_as_float(f2tf32(ra1.y));
        p[2] = __uint_as_float(f2tf32(ra1.z)); p[3] = __uint_as_float(f2tf32(ra1.w));
        p = &Bs[0][bk0 * BPAD + bc0];
        p[0] = __uint_as_float(f2tf32(rb0.x)); p[1] = __uint_as_float(f2tf32(rb0.y));
        p[2] = __uint_as_float(f2tf32(rb0.z)); p[3] = __uint_as_float(f2tf32(rb0.w));
        p = &Bs[0][bk1 * BPAD + bc1];
        p[0] = __uint_as_float(f2tf32(rb1.x)); p[1] = __uint_as_float(f2tf32(rb1.y));
        p[2] = __uint_as_float(f2tf32(rb1.z)); p[3] = __uint_as_float(f2tf32(rb1.w));
    }
    __syncthreads();

    int cur = 0;
    for (int k0 = 0; k0 < K; k0 += 16) {
        bool has_next = (k0 + 16) < K;
        if (has_next) {
            int kn = k0 + 16;
            ra0 = make_float4(0.f, 0.f, 0.f, 0.f);
            ra1 = ra0; rb0 = ra0; rb1 = ra0;
            if (bm + am0 < M) ra0 = *(const float4*)&A[(size_t)(bm + am0) * K + kn + ak0];
            if (bm + am1 < M) ra1 = *(const float4*)&A[(size_t)(bm + am1) * K + kn + ak1];
            if (bn + bc0 < N) rb0 = *(const float4*)&Bw[(size_t)(kn + bk0) * N + bn + bc0];
            if (bn + bc1 < N) rb1 = *(const float4*)&Bw[(size_t)(kn + bk1) * N + bn + bc1];
        }
        // compute on buffer cur
#pragma unroll
        for (int kk = 0; kk < 16; kk += 8) {
            unsigned af[2][4], bf[8][2];
#pragma unroll
            for (int mt = 0; mt < 2; mt++) {
                int row = wm * 32 + mt * 16 + gid;
                af[mt][0] = __float_as_uint(As[cur][row * APAD + kk + tig]);
                af[mt][1] = __float_as_uint(As[cur][(row + 8) * APAD + kk + tig]);
                af[mt][2] = __float_as_uint(As[cur][row * APAD + kk + tig + 4]);
                af[mt][3] = __float_as_uint(As[cur][(row + 8) * APAD + kk + tig + 4]);
            }
#pragma unroll
            for (int nt = 0; nt < 8; nt++) {
                int col = wn * 64 + nt * 8 + gid;
                bf[nt][0] = __float_as_uint(Bs[cur][(kk + tig) * BPAD + col]);
                bf[nt][1] = __float_as_uint(Bs[cur][(kk + tig + 4) * BPAD + col]);
            }
#pragma unroll
            for (int mt = 0; mt < 2; mt++)
#pragma unroll
                for (int nt = 0; nt < 8; nt++) {
                    asm volatile(
                        "mma.sync.aligned.m16n8k8.row.col.f32.tf32.tf32.f32 "
                        "{%0,%1,%2,%3}, {%4,%5,%6,%7}, {%8,%9}, {%0,%1,%2,%3};"
                        : "+f"(acc[mt][nt][0]), "+f"(acc[mt][nt][1]),
                          "+f"(acc[mt][nt][2]), "+f"(acc[mt][nt][3])
                        : "r"(af[mt][0]), "r"(af[mt][1]), "r"(af[mt][2]), "r"(af[mt][3]),
                          "r"(bf[nt][0]), "r"(bf[nt][1]));
                }
        }
        if (has_next) {
            int nb = cur ^ 1;
            float* p = &As[nb][am0 * APAD + ak0];
            p[0] = __uint_as_float(f2tf32(ra0.x)); p[1] = __uint_as_float(f2tf32(ra0.y));
            p[2] = __uint_as_float(f2tf32(ra0.z)); p[3] = __uint_as_float(f2tf32(ra0.w));
            p = &As[nb][am1 * APAD + ak1];
            p[0] = __uint_as_float(f2tf32(ra1.x)); p[1] = __uint_as_float(f2tf32(ra1.y));
            p[2] = __uint_as_float(f2tf32(ra1.z)); p[3] = __uint_as_float(f2tf32(ra1.w));
            p = &Bs[nb][bk0 * BPAD + bc0];
            p[0] = __uint_as_float(f2tf32(rb0.x)); p[1] = __uint_as_float(f2tf32(rb0.y));
            p[2] = __uint_as_float(f2tf32(rb0.z)); p[3] = __uint_as_float(f2tf32(rb0.w));
            p = &Bs[nb][bk1 * BPAD + bc1];
            p[0] = __uint_as_float(f2tf32(rb1.x)); p[1] = __uint_as_float(f2tf32(rb1.y));
            p[2] = __uint_as_float(f2tf32(rb1.z)); p[3] = __uint_as_float(f2tf32(rb1.w));
            __syncthreads();
            cur = nb;
        }
    }

#pragma unroll
    for (int mt = 0; mt < 2; mt++) {
#pragma unroll
        for (int nt = 0; nt < 8; nt++) {
            int col = bn + wn * 64 + nt * 8 + 2 * tig;
            if (col >= N) continue;
            int row0 = bm + wm * 32 + mt * 16 + gid;
            if (row0 < M)
                *(float2*)&C[(size_t)row0 * N + col] =
                    make_float2(acc[mt][nt][0], acc[mt][nt][1]);
            if (row0 + 8 < M)
                *(float2*)&C[(size_t)(row0 + 8) * N + col] =
                    make_float2(acc[mt][nt][2], acc[mt][nt][3]);
        }
    }
}

// ---- per-node attention logits (layers 2,3): warp per (n,h) ----
__global__ void attn_s(const float* __restrict__ h, const float* __restrict__ a_src,
                       const float* __restrict__ a_dst, int n, int H, int C) {
    int w = (blockIdx.x * blockDim.x + threadIdx.x) >> 5;
    int lane = threadIdx.x & 31;
    if (w >= n * H) return;
    int node = w / H, hd = w % H;
    const float* hp = h + (size_t)node * H * C + hd * C;
    float s1 = 0.f, s2 = 0.f;
    for (int c = lane; c < C; c += 32) {
        float v = hp[c];
        s1 += v * a_src[hd * C + c];
        s2 += v * a_dst[hd * C + c];
    }
#pragma unroll
    for (int o = 16; o; o >>= 1) {
        s1 += __shfl_xor_sync(0xFFFFFFFFu, s1, o);
        s2 += __shfl_xor_sync(0xFFFFFFFFu, s2, o);
    }
    if (!lane) { g_ssrc[w] = s1; g_sdst[w] = s2; }
}

// =====================================================================
// Warp-per-node GAT propagate (H=4, C=64): online softmax in registers,
// lane owns 8 channels (2 float4 LDG per edge), no block syncs.
// =====================================================================
__global__ __launch_bounds__(256) void gat_warp4(
    const float* __restrict__ h, const float* __restrict__ bias,
    float* __restrict__ out, int n, int do_relu) {
    __shared__ float sw[8][128];  // per-warp edge weights: 32 edges x 4 heads

    int wid = threadIdx.x >> 5, lane = threadIdx.x & 31;
    int node = blockIdx.x * 8 + wid;
    if (node >= n) return;
    int e0 = g_rowptr[node], e1 = g_rowptr[node + 1];
    float4 sd = *(const float4*)&g_sdst[node * 4];
    int hd = lane >> 3;  // head owned by this lane's channels

    float4 m4 = make_float4(NEG_INF, NEG_INF, NEG_INF, NEG_INF);
    float4 s4 = make_float4(0.f, 0.f, 0.f, 0.f);
    float4 acc0 = make_float4(0.f, 0.f, 0.f, 0.f);
    float4 acc1 = make_float4(0.f, 0.f, 0.f, 0.f);

    for (int c0 = e0; c0 < e1; c0 += 32) {
        int cs = min(32, e1 - c0);
        int src = 0;
        float4 lg = make_float4(NEG_INF, NEG_INF, NEG_INF, NEG_INF);
        if (lane < cs) {
            src = g_csr_src[c0 + lane];
            float4 ss = *(const float4*)&g_ssrc[src * 4];
            lg.x = ss.x + sd.x; lg.x = lg.x >= 0.f ? lg.x : 0.2f * lg.x;
            lg.y = ss.y + sd.y; lg.y = lg.y >= 0.f ? lg.y : 0.2f * lg.y;
            lg.z = ss.z + sd.z; lg.z = lg.z >= 0.f ? lg.z : 0.2f * lg.z;
            lg.w = ss.w + sd.w; lg.w = lg.w >= 0.f ? lg.w : 0.2f * lg.w;
        }
        // chunk max per head (warp-wide)
        float4 cm = lg;
#pragma unroll
        for (int o = 16; o; o >>= 1) {
            cm.x = fmaxf(cm.x, __shfl_xor_sync(0xFFFFFFFFu, cm.x, o));
            cm.y = fmaxf(cm.y, __shfl_xor_sync(0xFFFFFFFFu, cm.y, o));
            cm.z = fmaxf(cm.z, __shfl_xor_sync(0xFFFFFFFFu, cm.z, o));
            cm.w = fmaxf(cm.w, __shfl_xor_sync(0xFFFFFFFFu, cm.w, o));
        }
        float4 mnew = make_float4(fmaxf(m4.x, cm.x), fmaxf(m4.y, cm.y),
                                  fmaxf(m4.z, cm.z), fmaxf(m4.w, cm.w));
        float4 f = make_float4(__expf(m4.x - mnew.x), __expf(m4.y - mnew.y),
                               __expf(m4.z - mnew.z), __expf(m4.w - mnew.w));
        float fh = pick4(f, hd);
        acc0.x *= fh; acc0.y *= fh; acc0.z *= fh; acc0.w *= fh;
        acc1.x *= fh; acc1.y *= fh; acc1.z *= fh; acc1.w *= fh;
        s4.x *= f.x; s4.y *= f.y; s4.z *= f.z; s4.w *= f.w;
        m4 = mnew;
        float4 w = make_float4(0.f, 0.f, 0.f, 0.f);
        if (lane < cs) {
            w.x = __expf(lg.x - m4.x); w.y = __expf(lg.y - m4.y);
            w.z = __expf(lg.z - m4.z); w.w = __expf(lg.w - m4.w);
        }
        float4 ws = w;
#pragma unroll
        for (int o = 16; o; o >>= 1) {
            ws.x += __shfl_xor_sync(0xFFFFFFFFu, ws.x, o);
            ws.y += __shfl_xor_sync(0xFFFFFFFFu, ws.y, o);
            ws.z += __shfl_xor_sync(0xFFFFFFFFu, ws.z, o);
            ws.w += __shfl_xor_sync(0xFFFFFFFFu, ws.w, o);
        }
        s4.x += ws.x; s4.y += ws.y; s4.z += ws.z; s4.w += ws.w;
        *(float4*)&sw[wid][lane * 4] = w;
        __syncwarp();
        for (int e = 0; e < cs; e++) {
            int se = __shfl_sync(0xFFFFFFFFu, src, e);
            float we = sw[wid][e * 4 + hd];  // broadcast within 8-lane head group
            const float4* hp = (const float4*)(h + (size_t)se * 256);
            float4 v0 = hp[2 * lane], v1 = hp[2 * lane + 1];
            acc0.x += we * v0.x; acc0.y += we * v0.y;
            acc0.z += we * v0.z; acc0.w += we * v0.w;
            acc1.x += we * v1.x; acc1.y += we * v1.y;
            acc1.z += we * v1.z; acc1.w += we * v1.w;
        }
        __syncwarp();
    }
    float inv = 1.f / pick4(s4, hd);
    float4 b0 = *(const float4*)&bias[lane * 8];
    float4 b1 = *(const float4*)&bias[lane * 8 + 4];
    float4 o0, o1;
    o0.x = acc0.x * inv + b0.x; o0.y = acc0.y * inv + b0.y;
    o0.z = acc0.z * inv + b0.z; o0.w = acc0.w * inv + b0.w;
    o1.x = acc1.x * inv + b1.x; o1.y = acc1.y * inv + b1.y;
    o1.z = acc1.z * inv + b1.z; o1.w = acc1.w * inv + b1.w;
    if (do_relu) {
        o0.x = fmaxf(o0.x, 0.f); o0.y = fmaxf(o0.y, 0.f);
        o0.z = fmaxf(o0.z, 0.f); o0.w = fmaxf(o0.w, 0.f);
        o1.x = fmaxf(o1.x, 0.f); o1.y = fmaxf(o1.y, 0.f);
        o1.z = fmaxf(o1.z, 0.f); o1.w = fmaxf(o1.w, 0.f);
    }
    *(float4*)&out[(size_t)node * 256 + lane * 8] = o0;
    *(float4*)&out[(size_t)node * 256 + lane * 8 + 4] = o1;
}

// =====================================================================
// Fused GAT propagate (H=1, C=32): warp per dst node, all-shuffle.
// =====================================================================
__global__ void gat_fused1(const float* __restrict__ h, const float* __restrict__ bias,
                           float* __restrict__ out, int n) {
    int w = (blockIdx.x * blockDim.x + threadIdx.x) >> 5;
    int lane = threadIdx.x & 31;
    if (w >= n) return;
    int node = w;
    int e0 = g_rowptr[node], e1 = g_rowptr[node + 1];
    float sdst = g_sdst[node];
    float m = NEG_INF, s = 0.f, acc = 0.f;
    for (int c0 = e0; c0 < e1; c0 += 32) {
        int cs = min(32, e1 - c0);
        int src = (lane < cs) ? g_csr_src[c0 + lane] : 0;
        float v = NEG_INF;
        if (lane < cs) {
            v = g_ssrc[src] + sdst;
            v = v >= 0.f ? v : 0.2f * v;
        }
        float cm = v;
#pragma unroll
        for (int o = 16; o; o >>= 1) cm = fmaxf(cm, __shfl_xor_sync(0xFFFFFFFFu, cm, o));
        float mnew = fmaxf(m, cm);
        float f = __expf(m - mnew);
        acc *= f; s *= f; m = mnew;
        float wv = (lane < cs) ? __expf(v - m) : 0.f;
        float ps = wv;
#pragma unroll
        for (int o = 16; o; o >>= 1) ps += __shfl_xor_sync(0xFFFFFFFFu, ps, o);
        s += ps;
        for (int e = 0; e < cs; e++) {
            float we = __shfl_sync(0xFFFFFFFFu, wv, e);
            int se = __shfl_sync(0xFFFFFFFFu, src, e);
            acc += we * h[(size_t)se * 32 + lane];
        }
    }
    out[(size_t)node * 32 + lane] = acc / s + bias[lane];
}

extern "C" void kernel_launch(void* const* d_in, const int* in_sizes, int n_in,
                              void* d_out, int out_size) {
    const float* x      = (const float*)d_in[0];
    const int*   ei     = (const int*)d_in[1];
    const float* W1     = (const float*)d_in[2];
    const float* a_src1 = (const float*)d_in[3];
    const float* a_dst1 = (const float*)d_in[4];
    const float* b1     = (const float*)d_in[5];
    const float* W2     = (const float*)d_in[6];
    const float* a_src2 = (const float*)d_in[7];
    const float* a_dst2 = (const float*)d_in[8];
    const float* b2     = (const float*)d_in[9];
    const float* W3     = (const float*)d_in[10];
    const float* a_src3 = (const float*)d_in[11];
    const float* a_dst3 = (const float*)d_in[12];
    const float* b3     = (const float*)d_in[13];
    float* out = (float*)d_out;

    int n = in_sizes[0] / 3;
    int E = in_sizes[1] / 2;
    int Etot = E + n;

    float *gA, *gB;
    cudaGetSymbolAddress((void**)&gA, g_A);
    cudaGetSymbolAddress((void**)&gB, g_B);

    int nb = (n + 255) / 256;
    int nw8 = (n + 7) / 8;  // warp-per-node blocks (8 warps)
    int swb4 = (n * 4 + 7) / 8;
    int swb1 = (n * 1 + 7) / 8;
    dim3 g2((n + 127) / 128, 2);
    dim3 g3((n + 127) / 128, 1);

    // ---------------- CSR build (shared by all layers) ----------------
    csr_init<<<nb, 256>>>(n);
    csr_count<<<(E + 255) / 256, 256>>>(ei, E);
    scan_part<<<nb, 256>>>(n);
    scan_top<<<1, 256>>>(nb);
    scan_fin<<<nb, 256>>>(n);
    csr_fill<<<(Etot + 255) / 256, 256>>>(ei, E, Etot);

    // ---------------- Layer 1: x[N,3] -> [N,256], relu ----------------
    gemm_l1_attn<<<n, 256>>>(x, W1, a_src1, a_dst1, gB, n);
    gat_warp4<<<nw8, 256>>>(gB, b1, gA, n, 1);

    // ---------------- Layer 2: [N,256] -> [N,256], relu ---------------
    mma_gemm<<<g2, 256>>>(gA, W2, gB, n, 256, 256);
    attn_s<<<swb4, 256>>>(gB, a_src2, a_dst2, n, 4, 64);
    gat_warp4<<<nw8, 256>>>(gB, b2, gA, n, 1);

    // ---------------- Layer 3: [N,256] -> [N,32], mean ----------------
    mma_gemm<<<g3, 256>>>(gA, W3, gB, n, 32, 256);
    attn_s<<<swb1, 256>>>(gB, a_src3, a_dst3, n, 1, 32);
    gat_fused1<<<(n * 32 + 255) / 256, 256>>>(gB, b3, out, n);
}

// round 8
// speedup vs baseline: 2.6555x; 1.0983x over previous
#include <cuda_runtime.h>

#define NMAX 50000
#define EMAXE 400000
#define ETOTMAX (EMAXE + NMAX)
#define NEG_INF __int_as_float(0xff800000)

// Scratch (static device globals — allocation-free)
__device__ float g_A[NMAX * 256];       // feature buffer
__device__ float g_B[NMAX * 256];       // transformed features h = A @ W
__device__ float g_ssrc[NMAX * 4];      // per-node src attention logits [N,H]
__device__ float g_sdst[NMAX * 4];      // per-node dst attention logits [N,H]
__device__ int   g_csr_src[ETOTMAX];    // CSR: src ids grouped by dst
__device__ int   g_rowptr[NMAX + 1];    // CSR row pointers
__device__ int   g_wptr[NMAX];          // counts / write cursors (0 at start of every run)
__device__ int   g_blksum[260];         // scan partials

__device__ __forceinline__ unsigned f2tf32(float f) {
    unsigned u;
    asm("cvt.rna.tf32.f32 %0, %1;" : "=r"(u) : "f"(f));
    return u;
}

__device__ __forceinline__ float pick4(float4 v, int i) {
    float ab = (i & 1) ? v.y : v.x;
    float cd = (i & 1) ? v.w : v.z;
    return (i & 2) ? cd : ab;
}

// ============================ CSR construction ============================
// g_wptr is 0 at module load and re-zeroed by gemm_l1_attn each run.
__global__ void csr_count(const int* __restrict__ ei, int E) {
    int e = blockIdx.x * blockDim.x + threadIdx.x;
    if (e < E) atomicAdd(&g_wptr[ei[E + e]], 1);
}

// per-block sums of (count + 1)   [+1 = self-loop]
__global__ void scan_part(int n) {
    __shared__ int sm[256];
    int i = blockIdx.x * 256 + threadIdx.x;
    sm[threadIdx.x] = (i < n) ? g_wptr[i] + 1 : 0;
    __syncthreads();
    for (int o = 128; o; o >>= 1) {
        if (threadIdx.x < o) sm[threadIdx.x] += sm[threadIdx.x + o];
        __syncthreads();
    }
    if (!threadIdx.x) g_blksum[blockIdx.x] = sm[0];
}

// single-warp exclusive scan over <=256 block sums (no block barriers)
__global__ void scan_top(int nb) {
    int lane = threadIdx.x;
    int carry = 0;
    for (int base = 0; base < nb; base += 32) {
        int idx = base + lane;
        int v = (idx < nb) ? g_blksum[idx] : 0;
        int orig = v;
#pragma unroll
        for (int o = 1; o < 32; o <<= 1) {
            int t = __shfl_up_sync(0xFFFFFFFFu, v, o);
            if (lane >= o) v += t;
        }
        if (idx < nb) g_blksum[idx] = carry + v - orig;  // exclusive
        carry += __shfl_sync(0xFFFFFFFFu, v, 31);
    }
}

// per-block scan of (count+1) + global offset; reset cursors
__global__ void scan_fin(int n) {
    __shared__ int sm[256];
    int base = blockIdx.x * 256, tid = threadIdx.x, i = base + tid;
    int v = (i < n) ? g_wptr[i] + 1 : 0;
    sm[tid] = v;
    __syncthreads();
#pragma unroll
    for (int o = 1; o < 256; o <<= 1) {
        int t = (tid >= o) ? sm[tid - o] : 0;
        __syncthreads();
        sm[tid] += t;
        __syncthreads();
    }
    int incl = sm[tid];
    int off = g_blksum[blockIdx.x];
    if (i < n) { g_rowptr[i] = off + incl - v; g_wptr[i] = 0; }
    if (i == n - 1) g_rowptr[n] = off + incl;
}

__global__ void csr_fill(const int* __restrict__ ei, int E, int Etot) {
    int e = blockIdx.x * blockDim.x + threadIdx.x;
    if (e >= Etot) return;
    int s, d;
    if (e < E) { s = ei[e]; d = ei[E + e]; } else { s = d = e - E; }
    int pos = atomicAdd(&g_wptr[d], 1);
    g_csr_src[g_rowptr[d] + pos] = s;
}

// ============== layer 1 GEMM + fused attention logits ==============
// Also re-zeroes g_wptr (after csr_fill used it) for the next graph replay.
__global__ void gemm_l1_attn(const float* __restrict__ x, const float* __restrict__ W,
                             const float* __restrict__ asrc, const float* __restrict__ adst,
                             float* __restrict__ out, int n) {
    __shared__ float xs[3];
    __shared__ float r1[8], r2[8];
    int node = blockIdx.x;
    if (node >= n) return;
    int tid = threadIdx.x;
    if (tid < 3) xs[tid] = x[node * 3 + tid];
    if (tid == 32) g_wptr[node] = 0;  // cursor reset for next replay
    __syncthreads();
    float acc = xs[0] * W[tid] + xs[1] * W[256 + tid] + xs[2] * W[512 + tid];
    out[(size_t)node * 256 + tid] = acc;
    float p1 = acc * asrc[tid];
    float p2 = acc * adst[tid];
#pragma unroll
    for (int o = 16; o; o >>= 1) {
        p1 += __shfl_xor_sync(0xFFFFFFFFu, p1, o);
        p2 += __shfl_xor_sync(0xFFFFFFFFu, p2, o);
    }
    int warp = tid >> 5, lane = tid & 31;
    if (!lane) { r1[warp] = p1; r2[warp] = p2; }
    __syncthreads();
    if (tid < 4) {
        g_ssrc[node * 4 + tid] = r1[tid * 2] + r1[tid * 2 + 1];
        g_sdst[node * 4 + tid] = r2[tid * 2] + r2[tid * 2 + 1];
    }
}

// =====================================================================
// tf32 tensor-core GEMM, double-buffered smem, fused attn-logit epilogue.
// Each warp's 64-col range lies within one head -> warp-local reduction,
// direct stores of s_src/s_dst (no atomics).
// =====================================================================
#define APAD 20
#define BPAD 136

__global__ __launch_bounds__(256) void mma_gemm(
    const float* __restrict__ A, const float* __restrict__ Bw,
    float* __restrict__ C, int M, int N, int K,
    const float* __restrict__ asrc, const float* __restrict__ adst,
    int C_head, int H) {
    __shared__ float As[2][128 * APAD];
    __shared__ float Bs[2][16 * BPAD];

    int tid = threadIdx.x;
    int warp = tid >> 5, lane = tid & 31;
    int gid = lane >> 2, tig = lane & 3;
    int wm = warp & 3, wn = warp >> 2;
    int bm = blockIdx.x * 128, bn = blockIdx.y * 128;

    int am0 = (tid * 2) >> 2, ak0 = ((tid * 2) & 3) * 4;
    int am1 = (tid * 2 + 1) >> 2, ak1 = ((tid * 2 + 1) & 3) * 4;
    int bk0 = (tid * 2) >> 5, bc0 = ((tid * 2) & 31) * 4;
    int bk1 = (tid * 2 + 1) >> 5, bc1 = ((tid * 2 + 1) & 31) * 4;

    float acc[2][8][4];
#pragma unroll
    for (int i = 0; i < 2; i++)
#pragma unroll
        for (int j = 0; j < 8; j++)
#pragma unroll
            for (int r = 0; r < 4; r++) acc[i][j][r] = 0.f;

    float4 ra0, ra1, rb0, rb1;
    {
        ra0 = make_float4(0.f, 0.f, 0.f, 0.f);
        ra1 = ra0; rb0 = ra0; rb1 = ra0;
        if (bm + am0 < M) ra0 = *(const float4*)&A[(size_t)(bm + am0) * K + ak0];
        if (bm + am1 < M) ra1 = *(const float4*)&A[(size_t)(bm + am1) * K + ak1];
        if (bn + bc0 < N) rb0 = *(const float4*)&Bw[(size_t)bk0 * N + bn + bc0];
        if (bn + bc1 < N) rb1 = *(const float4*)&Bw[(size_t)bk1 * N + bn + bc1];
    }
    {
        float* p = &As[0][am0 * APAD + ak0];
        p[0] = __uint_as_float(f2tf32(ra0.x)); p[1] = __uint_as_float(f2tf32(ra0.y));
        p[2] = __uint_as_float(f2tf32(ra0.z)); p[3] = __uint_as_float(f2tf32(ra0.w));
        p = &As[0][am1 * APAD + ak1];
        p[0] = __uint_as_float(f2tf32(ra1.x)); p[1] = __uint_as_float(f2tf32(ra1.y));
        p[2] = __uint_as_float(f2tf32(ra1.z)); p[3] = __uint_as_float(f2tf32(ra1.w));
        p = &Bs[0][bk0 * BPAD + bc0];
        p[0] = __uint_as_float(f2tf32(rb0.x)); p[1] = __uint_as_float(f2tf32(rb0.y));
        p[2] = __uint_as_float(f2tf32(rb0.z)); p[3] = __uint_as_float(f2tf32(rb0.w));
        p = &Bs[0][bk1 * BPAD + bc1];
        p[0] = __uint_as_float(f2tf32(rb1.x)); p[1] = __uint_as_float(f2tf32(rb1.y));
        p[2] = __uint_as_float(f2tf32(rb1.z)); p[3] = __uint_as_float(f2tf32(rb1.w));
    }
    __syncthreads();

    int cur = 0;
    for (int k0 = 0; k0 < K; k0 += 16) {
        bool has_next = (k0 + 16) < K;
        if (has_next) {
            int kn = k0 + 16;
            ra0 = make_float4(0.f, 0.f, 0.f, 0.f);
            ra1 = ra0; rb0 = ra0; rb1 = ra0;
            if (bm + am0 < M) ra0 = *(const float4*)&A[(size_t)(bm + am0) * K + kn + ak0];
            if (bm + am1 < M) ra1 = *(const float4*)&A[(size_t)(bm + am1) * K + kn + ak1];
            if (bn + bc0 < N) rb0 = *(const float4*)&Bw[(size_t)(kn + bk0) * N + bn + bc0];
            if (bn + bc1 < N) rb1 = *(const float4*)&Bw[(size_t)(kn + bk1) * N + bn + bc1];
        }
#pragma unroll
        for (int kk = 0; kk < 16; kk += 8) {
            unsigned af[2][4], bf[8][2];
#pragma unroll
            for (int mt = 0; mt < 2; mt++) {
                int row = wm * 32 + mt * 16 + gid;
                af[mt][0] = __float_as_uint(As[cur][row * APAD + kk + tig]);
                af[mt][1] = __float_as_uint(As[cur][(row + 8) * APAD + kk + tig]);
                af[mt][2] = __float_as_uint(As[cur][row * APAD + kk + tig + 4]);
                af[mt][3] = __float_as_uint(As[cur][(row + 8) * APAD + kk + tig + 4]);
            }
#pragma unroll
            for (int nt = 0; nt < 8; nt++) {
                int col = wn * 64 + nt * 8 + gid;
                bf[nt][0] = __float_as_uint(Bs[cur][(kk + tig) * BPAD + col]);
                bf[nt][1] = __float_as_uint(Bs[cur][(kk + tig + 4) * BPAD + col]);
            }
#pragma unroll
            for (int mt = 0; mt < 2; mt++)
#pragma unroll
                for (int nt = 0; nt < 8; nt++) {
                    asm volatile(
                        "mma.sync.aligned.m16n8k8.row.col.f32.tf32.tf32.f32 "
                        "{%0,%1,%2,%3}, {%4,%5,%6,%7}, {%8,%9}, {%0,%1,%2,%3};"
                        : "+f"(acc[mt][nt][0]), "+f"(acc[mt][nt][1]),
                          "+f"(acc[mt][nt][2]), "+f"(acc[mt][nt][3])
                        : "r"(af[mt][0]), "r"(af[mt][1]), "r"(af[mt][2]), "r"(af[mt][3]),
                          "r"(bf[nt][0]), "r"(bf[nt][1]));
                }
        }
        if (has_next) {
            int nb = cur ^ 1;
            float* p = &As[nb][am0 * APAD + ak0];
            p[0] = __uint_as_float(f2tf32(ra0.x)); p[1] = __uint_as_float(f2tf32(ra0.y));
            p[2] = __uint_as_float(f2tf32(ra0.z)); p[3] = __uint_as_float(f2tf32(ra0.w));
            p = &As[nb][am1 * APAD + ak1];
            p[0] = __uint_as_float(f2tf32(ra1.x)); p[1] = __uint_as_float(f2tf32(ra1.y));
            p[2] = __uint_as_float(f2tf32(ra1.z)); p[3] = __uint_as_float(f2tf32(ra1.w));
            p = &Bs[nb][bk0 * BPAD + bc0];
            p[0] = __uint_as_float(f2tf32(rb0.x)); p[1] = __uint_as_float(f2tf32(rb0.y));
            p[2] = __uint_as_float(f2tf32(rb0.z)); p[3] = __uint_as_float(f2tf32(rb0.w));
            p = &Bs[nb][bk1 * BPAD + bc1];
            p[0] = __uint_as_float(f2tf32(rb1.x)); p[1] = __uint_as_float(f2tf32(rb1.y));
            p[2] = __uint_as_float(f2tf32(rb1.z)); p[3] = __uint_as_float(f2tf32(rb1.w));
            __syncthreads();
            cur = nb;
        }
    }

    // ---------------- store C ----------------
#pragma unroll
    for (int mt = 0; mt < 2; mt++) {
#pragma unroll
        for (int nt = 0; nt < 8; nt++) {
            int col = bn + wn * 64 + nt * 8 + 2 * tig;
            if (col >= N) continue;
            int row0 = bm + wm * 32 + mt * 16 + gid;
            if (row0 < M)
                *(float2*)&C[(size_t)row0 * N + col] =
                    make_float2(acc[mt][nt][0], acc[mt][nt][1]);
            if (row0 + 8 < M)
                *(float2*)&C[(size_t)(row0 + 8) * N + col] =
                    make_float2(acc[mt][nt][2], acc[mt][nt][3]);
        }
    }

    // ------------- fused attention-logit epilogue -------------
    // warp column base
    int wcb = bn + wn * 64;
    if (wcb < N) {
        int hd = wcb / C_head;
        // per-thread partials for 4 rows: [mt][half]
        float psrc[2][2] = {{0.f, 0.f}, {0.f, 0.f}};
        float pdst[2][2] = {{0.f, 0.f}, {0.f, 0.f}};
#pragma unroll
        for (int nt = 0; nt < 8; nt++) {
            int col = wcb + nt * 8 + 2 * tig;
            if (col >= N) continue;
            int cih = col - hd * C_head;
            float a0s = asrc[hd * C_head + cih], a1s = asrc[hd * C_head + cih + 1];
            float a0d = adst[hd * C_head + cih], a1d = adst[hd * C_head + cih + 1];
#pragma unroll
            for (int mt = 0; mt < 2; mt++) {
                psrc[mt][0] += acc[mt][nt][0] * a0s + acc[mt][nt][1] * a1s;
                pdst[mt][0] += acc[mt][nt][0] * a0d + acc[mt][nt][1] * a1d;
                psrc[mt][1] += acc[mt][nt][2] * a0s + acc[mt][nt][3] * a1s;
                pdst[mt][1] += acc[mt][nt][2] * a0d + acc[mt][nt][3] * a1d;
            }
        }
        // reduce over tig (lanes gid*4+{0..3})
#pragma unroll
        for (int o = 1; o < 4; o <<= 1) {
#pragma unroll
            for (int mt = 0; mt < 2; mt++) {
#pragma unroll
                for (int hf = 0; hf < 2; hf++) {
                    psrc[mt][hf] += __shfl_xor_sync(0xFFFFFFFFu, psrc[mt][hf], o);
                    pdst[mt][hf] += __shfl_xor_sync(0xFFFFFFFFu, pdst[mt][hf], o);
                }
            }
        }
        if (tig == 0) {
#pragma unroll
            for (int mt = 0; mt < 2; mt++) {
#pragma unroll
                for (int hf = 0; hf < 2; hf++) {
                    int row = bm + wm * 32 + mt * 16 + gid + hf * 8;
                    if (row < M) {
                        g_ssrc[row * H + hd] = psrc[mt][hf];
                        g_sdst[row * H + hd] = pdst[mt][hf];
                    }
                }
            }
        }
    }
}

// =====================================================================
// Warp-per-node GAT propagate (H=4, C=64)
// =====================================================================
__global__ __launch_bounds__(256) void gat_warp4(
    const float* __restrict__ h, const float* __restrict__ bias,
    float* __restrict__ out, int n, int do_relu) {
    __shared__ float sw[8][128];

    int wid = threadIdx.x >> 5, lane = threadIdx.x & 31;
    int node = blockIdx.x * 8 + wid;
    if (node >= n) return;
    int e0 = g_rowptr[node], e1 = g_rowptr[node + 1];
    float4 sd = *(const float4*)&g_sdst[node * 4];
    int hd = lane >> 3;

    float4 m4 = make_float4(NEG_INF, NEG_INF, NEG_INF, NEG_INF);
    float4 s4 = make_float4(0.f, 0.f, 0.f, 0.f);
    float4 acc0 = make_float4(0.f, 0.f, 0.f, 0.f);
    float4 acc1 = make_float4(0.f, 0.f, 0.f, 0.f);

    for (int c0 = e0; c0 < e1; c0 += 32) {
        int cs = min(32, e1 - c0);
        int src = 0;
        float4 lg = make_float4(NEG_INF, NEG_INF, NEG_INF, NEG_INF);
        if (lane < cs) {
            src = g_csr_src[c0 + lane];
            float4 ss = *(const float4*)&g_ssrc[src * 4];
            lg.x = ss.x + sd.x; lg.x = lg.x >= 0.f ? lg.x : 0.2f * lg.x;
            lg.y = ss.y + sd.y; lg.y = lg.y >= 0.f ? lg.y : 0.2f * lg.y;
            lg.z = ss.z + sd.z; lg.z = lg.z >= 0.f ? lg.z : 0.2f * lg.z;
            lg.w = ss.w + sd.w; lg.w = lg.w >= 0.f ? lg.w : 0.2f * lg.w;
        }
        float4 cm = lg;
#pragma unroll
        for (int o = 16; o; o >>= 1) {
            cm.x = fmaxf(cm.x, __shfl_xor_sync(0xFFFFFFFFu, cm.x, o));
            cm.y = fmaxf(cm.y, __shfl_xor_sync(0xFFFFFFFFu, cm.y, o));
            cm.z = fmaxf(cm.z, __shfl_xor_sync(0xFFFFFFFFu, cm.z, o));
            cm.w = fmaxf(cm.w, __shfl_xor_sync(0xFFFFFFFFu, cm.w, o));
        }
        float4 mnew = make_float4(fmaxf(m4.x, cm.x), fmaxf(m4.y, cm.y),
                                  fmaxf(m4.z, cm.z), fmaxf(m4.w, cm.w));
        float4 f = make_float4(__expf(m4.x - mnew.x), __expf(m4.y - mnew.y),
                               __expf(m4.z - mnew.z), __expf(m4.w - mnew.w));
        float fh = pick4(f, hd);
        acc0.x *= fh; acc0.y *= fh; acc0.z *= fh; acc0.w *= fh;
        acc1.x *= fh; acc1.y *= fh; acc1.z *= fh; acc1.w *= fh;
        s4.x *= f.x; s4.y *= f.y; s4.z *= f.z; s4.w *= f.w;
        m4 = mnew;
        float4 w = make_float4(0.f, 0.f, 0.f, 0.f);
        if (lane < cs) {
            w.x = __expf(lg.x - m4.x); w.y = __expf(lg.y - m4.y);
            w.z = __expf(lg.z - m4.z); w.w = __expf(lg.w - m4.w);
        }
        float4 ws = w;
#pragma unroll
        for (int o = 16; o; o >>= 1) {
            ws.x += __shfl_xor_sync(0xFFFFFFFFu, ws.x, o);
            ws.y += __shfl_xor_sync(0xFFFFFFFFu, ws.y, o);
            ws.z += __shfl_xor_sync(0xFFFFFFFFu, ws.z, o);
            ws.w += __shfl_xor_sync(0xFFFFFFFFu, ws.w, o);
        }
        s4.x += ws.x; s4.y += ws.y; s4.z += ws.z; s4.w += ws.w;
        *(float4*)&sw[wid][lane * 4] = w;
        __syncwarp();
        for (int e = 0; e < cs; e++) {
            int se = __shfl_sync(0xFFFFFFFFu, src, e);
            float we = sw[wid][e * 4 + hd];
            const float4* hp = (const float4*)(h + (size_t)se * 256);
            float4 v0 = hp[2 * lane], v1 = hp[2 * lane + 1];
            acc0.x += we * v0.x; acc0.y += we * v0.y;
            acc0.z += we * v0.z; acc0.w += we * v0.w;
            acc1.x += we * v1.x; acc1.y += we * v1.y;
            acc1.z += we * v1.z; acc1.w += we * v1.w;
        }
        __syncwarp();
    }
    float inv = 1.f / pick4(s4, hd);
    float4 b0 = *(const float4*)&bias[lane * 8];
    float4 b1 = *(const float4*)&bias[lane * 8 + 4];
    float4 o0, o1;
    o0.x = acc0.x * inv + b0.x; o0.y = acc0.y * inv + b0.y;
    o0.z = acc0.z * inv + b0.z; o0.w = acc0.w * inv + b0.w;
    o1.x = acc1.x * inv + b1.x; o1.y = acc1.y * inv + b1.y;
    o1.z = acc1.z * inv + b1.z; o1.w = acc1.w * inv + b1.w;
    if (do_relu) {
        o0.x = fmaxf(o0.x, 0.f); o0.y = fmaxf(o0.y, 0.f);
        o0.z = fmaxf(o0.z, 0.f); o0.w = fmaxf(o0.w, 0.f);
        o1.x = fmaxf(o1.x, 0.f); o1.y = fmaxf(o1.y, 0.f);
        o1.z = fmaxf(o1.z, 0.f); o1.w = fmaxf(o1.w, 0.f);
    }
    *(float4*)&out[(size_t)node * 256 + lane * 8] = o0;
    *(float4*)&out[(size_t)node * 256 + lane * 8 + 4] = o1;
}

// =====================================================================
// Fused GAT propagate (H=1, C=32): warp per dst node, all-shuffle.
// =====================================================================
__global__ void gat_fused1(const float* __restrict__ h, const float* __restrict__ bias,
                           float* __restrict__ out, int n) {
    int w = (blockIdx.x * blockDim.x + threadIdx.x) >> 5;
    int lane = threadIdx.x & 31;
    if (w >= n) return;
    int node = w;
    int e0 = g_rowptr[node], e1 = g_rowptr[node + 1];
    float sdst = g_sdst[node];
    float m = NEG_INF, s = 0.f, acc = 0.f;
    for (int c0 = e0; c0 < e1; c0 += 32) {
        int cs = min(32, e1 - c0);
        int src = (lane < cs) ? g_csr_src[c0 + lane] : 0;
        float v = NEG_INF;
        if (lane < cs) {
            v = g_ssrc[src] + sdst;
            v = v >= 0.f ? v : 0.2f * v;
        }
        float cm = v;
#pragma unroll
        for (int o = 16; o; o >>= 1) cm = fmaxf(cm, __shfl_xor_sync(0xFFFFFFFFu, cm, o));
        float mnew = fmaxf(m, cm);
        float f = __expf(m - mnew);
        acc *= f; s *= f; m = mnew;
        float wv = (lane < cs) ? __expf(v - m) : 0.f;
        float ps = wv;
#pragma unroll
        for (int o = 16; o; o >>= 1) ps += __shfl_xor_sync(0xFFFFFFFFu, ps, o);
        s += ps;
        for (int e = 0; e < cs; e++) {
            float we = __shfl_sync(0xFFFFFFFFu, wv, e);
            int se = __shfl_sync(0xFFFFFFFFu, src, e);
            acc += we * h[(size_t)se * 32 + lane];
        }
    }
    out[(size_t)node * 32 + lane] = acc / s + bias[lane];
}

extern "C" void kernel_launch(void* const* d_in, const int* in_sizes, int n_in,
                              void* d_out, int out_size) {
    const float* x      = (const float*)d_in[0];
    const int*   ei     = (const int*)d_in[1];
    const float* W1     = (const float*)d_in[2];
    const float* a_src1 = (const float*)d_in[3];
    const float* a_dst1 = (const float*)d_in[4];
    const float* b1     = (const float*)d_in[5];
    const float* W2     = (const float*)d_in[6];
    const float* a_src2 = (const float*)d_in[7];
    const float* a_dst2 = (const float*)d_in[8];
    const float* b2     = (const float*)d_in[9];
    const float* W3     = (const float*)d_in[10];
    const float* a_src3 = (const float*)d_in[11];
    const float* a_dst3 = (const float*)d_in[12];
    const float* b3     = (const float*)d_in[13];
    float* out = (float*)d_out;

    int n = in_sizes[0] / 3;
    int E = in_sizes[1] / 2;
    int Etot = E + n;

    float *gA, *gB;
    cudaGetSymbolAddress((void**)&gA, g_A);
    cudaGetSymbolAddress((void**)&gB, g_B);

    int nb = (n + 255) / 256;
    int nw8 = (n + 7) / 8;
    dim3 g2((n + 127) / 128, 2);
    dim3 g3((n + 127) / 128, 1);

    // ---------------- CSR build (5 kernels) ----------------
    csr_count<<<(E + 255) / 256, 256>>>(ei, E);
    scan_part<<<nb, 256>>>(n);
    scan_top<<<1, 32>>>(nb);
    scan_fin<<<nb, 256>>>(n);
    csr_fill<<<(Etot + 255) / 256, 256>>>(ei, E, Etot);

    // ---------------- Layer 1: x[N,3] -> [N,256], relu ----------------
    gemm_l1_attn<<<n, 256>>>(x, W1, a_src1, a_dst1, gB, n);
    gat_warp4<<<nw8, 256>>>(gB, b1, gA, n, 1);

    // ---------------- Layer 2: [N,256] -> [N,256], relu ---------------
    mma_gemm<<<g2, 256>>>(gA, W2, gB, n, 256, 256, a_src2, a_dst2, 64, 4);
    gat_warp4<<<nw8, 256>>>(gB, b2, gA, n, 1);

    // ---------------- Layer 3: [N,256] -> [N,32], mean ----------------
    mma_gemm<<<g3, 256>>>(gA, W3, gB, n, 32, 256, a_src3, a_dst3, 32, 1);
    gat_fused1<<<(n * 32 + 255) / 256, 256>>>(gB, b3, out, n);
}